// round 16
// baseline (speedup 1.0000x reference)
#include <cuda_runtime.h>
#include <cuda_bf16.h>
#include <cstdint>
#include <cstddef>

// ---------------- problem dims ----------------
#define BS 4096
#define IN 2056
#define MF 24
#define H 4
#define HE 128
#define E 64
#define NA 128
#define RNN 256
#define KTOT 8192

// ---------------- scratch ----------------
__device__ float g_hid[BS * 192];
__device__ float g_bt[BS];
__device__ float g_q[BS * H * E];
__device__ float g_km[BS * H * E];
__device__ float g_vm[BS * H * E];
__device__ float g_te[BS * 64];
__device__ float g_ta[BS * 64];
__device__ float g_S[RNN];
__device__ float g_part[(size_t)4 * BS * RNN];
__device__ __align__(16) __nv_bfloat16 g_Abf[(size_t)BS * KTOT];
__device__ __align__(16) __nv_bfloat16 g_Wfbf[(size_t)RNN * KTOT];
__device__ __align__(16) __nv_bfloat16 g_Wvbf[2 * 64 * 64];

// ---------------- PTX helpers ----------------
__device__ __forceinline__ uint32_t smem_u32(const void* p) {
    uint32_t a;
    asm("{ .reg .u64 t; cvta.to.shared.u64 t, %1; cvt.u32.u64 %0, t; }" : "=r"(a) : "l"(p));
    return a;
}
__device__ __forceinline__ void cp16(uint32_t dst, const void* src) {
    asm volatile("cp.async.cg.shared.global [%0], [%1], 16;" :: "r"(dst), "l"(src) : "memory");
}
#define CP_COMMIT() asm volatile("cp.async.commit_group;" ::: "memory")
#define CP_WAIT(n)  asm volatile("cp.async.wait_group %0;" :: "n"(n) : "memory")

#define LDSM_X4(r0, r1, r2, r3, addr) \
    asm volatile("ldmatrix.sync.aligned.m8n8.x4.shared.b16 {%0,%1,%2,%3}, [%4];" \
                 : "=r"(r0), "=r"(r1), "=r"(r2), "=r"(r3) : "r"(addr))

#define MMA16816(d, a, b) \
    asm volatile("mma.sync.aligned.m16n8k16.row.col.f32.bf16.bf16.f32 " \
                 "{%0,%1,%2,%3}, {%4,%5,%6,%7}, {%8,%9}, {%0,%1,%2,%3};" \
                 : "+f"((d)[0]), "+f"((d)[1]), "+f"((d)[2]), "+f"((d)[3]) \
                 : "r"((a)[0]), "r"((a)[1]), "r"((a)[2]), "r"((a)[3]), \
                   "r"((b)[0]), "r"((b)[1]))

#define SWZ(x) ((x) ^ (((x) >> 3) & 0x70))

__device__ __forceinline__ uint32_t packbf2(float x, float y) {
    __nv_bfloat162 p = __floats2bfloat162_rn(x, y);
    return *(uint32_t*)&p;
}

// =====================================================================
// K0: m-MLPs (384 blocks); mlp==0 also computes te/ta via mma
// =====================================================================
__global__ __launch_bounds__(256) void k_prep_mlp(
        const float* __restrict__ obs,
        const float* __restrict__ Wq1, const float* __restrict__ bq1,
        const float* __restrict__ Wq2,
        const float* __restrict__ Wkm1, const float* __restrict__ bkm1,
        const float* __restrict__ Wkm2,
        const float* __restrict__ Wvm1, const float* __restrict__ bvm1,
        const float* __restrict__ Wvm2,
        const float* __restrict__ Wke, const float* __restrict__ Wka) {
    extern __shared__ __align__(128) char smp[];
    int idx = blockIdx.x;
    int tid = threadIdx.x;
    const int bm = (idx & 31) * 128;
    int yy = idx >> 5;
    const int mlp = yy >> 2, h = yy & 3;
    const int lane = tid & 31;

    float* msm = (float*)smp;
    float* w1s = (float*)(smp + 12800);
    float* b1s = (float*)(smp + 25600);
    char* h1B = smp + 26112;
    char* w2B = smp + 58880;

    const float* W1 = ((mlp == 0) ? Wq1 : (mlp == 1) ? Wkm1 : Wvm1) + h * HE * MF;
    const float* B1 = ((mlp == 0) ? bq1 : (mlp == 1) ? bkm1 : bvm1) + h * HE;
    const float* W2 = ((mlp == 0) ? Wq2 : (mlp == 1) ? Wkm2 : Wvm2) + h * E * HE;
    float* outp = (mlp == 0) ? g_q : (mlp == 1) ? g_km : g_vm;

    for (int i = tid; i < 128 * 24; i += 256) {
        int rr = i / 24, f = i - rr * 24;
        int col = (f < 4) ? f : (2032 + f);
        msm[rr * 25 + f] = obs[(size_t)(bm + rr) * IN + col];
    }
    for (int i = tid; i < 128 * 24; i += 256) {
        int g = i / 24, f = i - g * 24;
        w1s[g * 25 + f] = W1[g * 24 + f];
    }
    if (tid < 128) b1s[tid] = B1[tid];
    for (int i = tid; i < 1024; i += 256) {
        int e = i >> 4, g8 = (i & 15) * 8;
        int kk = g8 >> 6, wi = g8 & 63;
        const float* src = W2 + e * HE + g8;
        float4 v0 = *(const float4*)src;
        float4 v1 = *(const float4*)(src + 4);
        __nv_bfloat162 p[4];
        p[0] = __floats2bfloat162_rn(v0.x, v0.y);
        p[1] = __floats2bfloat162_rn(v0.z, v0.w);
        p[2] = __floats2bfloat162_rn(v1.x, v1.y);
        p[3] = __floats2bfloat162_rn(v1.z, v1.w);
        *(uint4*)(w2B + kk * 8192 + SWZ((uint32_t)(e * 128 + wi * 2))) = *(uint4*)p;
    }
    __syncthreads();

    {
        int rr = tid & 127, chalf = tid >> 7;
        float mreg[24];
        #pragma unroll
        for (int f = 0; f < 24; f++) mreg[f] = msm[rr * 25 + f];
        char* pan = h1B + chalf * 16384;
        #pragma unroll 4
        for (int c = 0; c < 64; c += 2) {
            int cc = chalf * 64 + c;
            float a0 = b1s[cc], a1 = b1s[cc + 1];
            const float* w0 = w1s + cc * 25;
            #pragma unroll
            for (int f = 0; f < 24; f++) {
                a0 += mreg[f] * w0[f];
                a1 += mreg[f] * w0[25 + f];
            }
            __nv_bfloat162 p = __floats2bfloat162_rn(fmaxf(a0, 0.f), fmaxf(a1, 0.f));
            *(__nv_bfloat162*)(pan + SWZ((uint32_t)(rr * 128 + c * 2))) = p;
        }
    }
    __syncthreads();

    {
        int w = tid >> 5;
        int wm = (w & 1) * 64, wn = (w >> 1) * 16;
        uint32_t h1b = smem_u32(h1B);
        uint32_t w2b = smem_u32(w2B);
        float d[4][2][4] = {};
        #pragma unroll
        for (int kk = 0; kk < 2; kk++) {
            uint32_t ab = h1b + kk * 16384;
            uint32_t bb = w2b + kk * 8192;
            #pragma unroll
            for (int ks = 0; ks < 4; ks++) {
                uint32_t bfr[2][2];
                {
                    uint32_t by = (uint32_t)((wn + (lane & 15)) * 128 + (lane >> 4) * 16 + ks * 32);
                    uint32_t r0, r1, r2, r3;
                    LDSM_X4(r0, r1, r2, r3, bb + SWZ(by));
                    bfr[0][0] = r0; bfr[0][1] = r2;
                    bfr[1][0] = r1; bfr[1][1] = r3;
                }
                #pragma unroll
                for (int mt = 0; mt < 4; mt++) {
                    uint32_t a[4];
                    uint32_t by = (uint32_t)((wm + mt * 16 + (lane & 15)) * 128
                                             + (lane >> 4) * 16 + ks * 32);
                    LDSM_X4(a[0], a[1], a[2], a[3], ab + SWZ(by));
                    MMA16816(d[mt][0], a, bfr[0]);
                    MMA16816(d[mt][1], a, bfr[1]);
                }
            }
        }
        #pragma unroll
        for (int mt = 0; mt < 4; mt++)
            #pragma unroll
            for (int half = 0; half < 2; half++) {
                int row = bm + wm + mt * 16 + half * 8 + (lane >> 2);
                #pragma unroll
                for (int nt = 0; nt < 2; nt++) {
                    int e = wn + nt * 8 + (lane & 3) * 2;
                    *(float2*)&outp[(size_t)row * 256 + h * 64 + e] =
                        make_float2(d[mt][nt][half * 2], d[mt][nt][half * 2 + 1]);
                }
            }

        if (mlp == 0) {
            __syncthreads();
            char* qB = h1B;
            #pragma unroll
            for (int mt = 0; mt < 4; mt++)
                #pragma unroll
                for (int half = 0; half < 2; half++) {
                    int rl = wm + mt * 16 + half * 8 + (lane >> 2);
                    #pragma unroll
                    for (int nt = 0; nt < 2; nt++) {
                        int e = wn + nt * 8 + (lane & 3) * 2;
                        *(__nv_bfloat162*)(qB + SWZ((uint32_t)(rl * 128 + e * 2))) =
                            __floats2bfloat162_rn(d[mt][nt][half * 2], d[mt][nt][half * 2 + 1]);
                    }
                }
            for (int i = tid; i < 2048; i += 256) {
                int row = i >> 6, e = i & 63;
                int dd = row & 15;
                const float* Wk = (row < 16) ? Wke : Wka;
                *(__nv_bfloat16*)(w2B + SWZ((uint32_t)(row * 128 + e * 2))) =
                    __float2bfloat16_rn(Wk[h * 1024 + e * 16 + dd]);
            }
            __syncthreads();
            int wm2 = w * 16;
            uint32_t ab2 = smem_u32(qB);
            uint32_t bb3 = smem_u32(w2B);
            float dd[4][4] = {};
            #pragma unroll
            for (int ks = 0; ks < 4; ks++) {
                uint32_t a[4];
                uint32_t by = (uint32_t)((wm2 + (lane & 15)) * 128 + (lane >> 4) * 16 + ks * 32);
                LDSM_X4(a[0], a[1], a[2], a[3], ab2 + SWZ(by));
                uint32_t bfr[4][2];
                #pragma unroll
                for (int nr = 0; nr < 2; nr++) {
                    uint32_t by2 = (uint32_t)((nr * 16 + (lane & 15)) * 128
                                              + (lane >> 4) * 16 + ks * 32);
                    uint32_t r0, r1, r2, r3;
                    LDSM_X4(r0, r1, r2, r3, bb3 + SWZ(by2));
                    bfr[nr * 2][0] = r0; bfr[nr * 2][1] = r2;
                    bfr[nr * 2 + 1][0] = r1; bfr[nr * 2 + 1][1] = r3;
                }
                #pragma unroll
                for (int nt = 0; nt < 4; nt++) MMA16816(dd[nt], a, bfr[nt]);
            }
            #pragma unroll
            for (int half = 0; half < 2; half++) {
                int bglob = bm + wm2 + half * 8 + (lane >> 2);
                #pragma unroll
                for (int nt = 0; nt < 4; nt++) {
                    int n = nt * 8 + (lane & 3) * 2;
                    float v0 = dd[nt][half * 2] * 0.125f;
                    float v1 = dd[nt][half * 2 + 1] * 0.125f;
                    float* dst = (n < 16) ? (g_te + bglob * 64 + h * 16 + n)
                                          : (g_ta + bglob * 64 + h * 16 + (n - 16));
                    *(float2*)dst = make_float2(v0, v1);
                }
            }
        }
    }
}

// =====================================================================
// K1: front GEMM (blocks 0..191, A AND B converted in-register)
//     + Wf permute/S (192..447) + Wv flatten (448)
// =====================================================================
__global__ __launch_bounds__(256) void k_front_tc(const float* __restrict__ obs,
                                                  const float* __restrict__ bb1,
                                                  const float* __restrict__ bh1,
                                                  const float* __restrict__ Wb1,
                                                  const float* __restrict__ Wh1,
                                                  const float* __restrict__ Wf,
                                                  const float* __restrict__ Wve,
                                                  const float* __restrict__ Wva) {
    __shared__ __align__(128) char sm8[49152];
    const int tid = threadIdx.x;
    const int blk = blockIdx.x;

    if (blk >= 192) {
        if (blk < 448) {
            int r = blk - 192;
            float* row = (float*)sm8;
            float* red = (float*)sm8 + 8256;
            float s = 0.f;
            for (int i = tid; i < 8192; i += 256) {
                float v = Wf[(size_t)r * 8192 + i];
                row[i + (i >> 7)] = v;
                s += v;
            }
            #pragma unroll
            for (int o = 16; o; o >>= 1) s += __shfl_xor_sync(0xffffffffu, s, o);
            if ((tid & 31) == 0) red[tid >> 5] = s;
            __syncthreads();
            if (tid == 0) {
                float t = 0.f;
                #pragma unroll
                for (int j = 0; j < 8; j++) t += red[j];
                g_S[r] = t;
            }
            for (int i = tid; i < 8192; i += 256) {
                int na = i >> 6, e = i & 63;
                int src = e * 128 + na;
                g_Wfbf[(size_t)r * 8192 + i] = __float2bfloat16_rn(row[src + (src >> 7)]);
            }
        } else {
            for (int i = tid; i < 8192; i += 256) {
                int sel = i >> 12, j = i & 4095;
                int e = j >> 6, hd = j & 63, h = hd >> 4, d = hd & 15;
                const float* W = sel ? Wva : Wve;
                g_Wvbf[i] = __float2bfloat16_rn(W[h * 1024 + e * 16 + d]);
            }
        }
        return;
    }

    const int lane = tid & 31, w = tid >> 5;
    const int bm = (blk & 63) * 64, bn = (blk >> 6) * 64;
    const int wm = (w & 3) * 16, wn = (w >> 2) * 32;
    float d[4][4] = {};

    const int row0 = tid >> 3, c16_0 = tid & 7;
    const int row1 = (tid + 256) >> 3, c16_1 = (tid + 256) & 7;
    const float* Wr0 = (bn + row0 < 64) ? (Wb1 + (size_t)(bn + row0) * IN)
                                        : (Wh1 + (size_t)(bn + row0 - 64) * IN);
    const float* Wr1 = (bn + row1 < 64) ? (Wb1 + (size_t)(bn + row1) * IN)
                                        : (Wh1 + (size_t)(bn + row1 - 64) * IN);
    float4 areg[2], breg[2];

    auto ldAB = [&](int t) {
        int k0 = t * 32 + c16_0 * 4;
        int k1 = t * 32 + c16_1 * 4;
        float4 z = make_float4(0.f, 0.f, 0.f, 0.f);
        areg[0] = (k0 < IN) ? *(const float4*)(obs + (size_t)(bm + row0) * IN + k0) : z;
        areg[1] = (k1 < IN) ? *(const float4*)(obs + (size_t)(bm + row1) * IN + k1) : z;
        breg[0] = (k0 < IN) ? *(const float4*)(Wr0 + k0) : z;
        breg[1] = (k1 < IN) ? *(const float4*)(Wr1 + k1) : z;
    };
    auto stAB = [&](int buf) {
        #pragma unroll
        for (int i = 0; i < 2; i++) {
            int row = i ? row1 : row0, c16 = i ? c16_1 : c16_0;
            uint32_t off = SWZ((uint32_t)(row * 128 + c16 * 16));
            // A: (hi, lo) interleaved
            {
                float xs[4] = {areg[i].x, areg[i].y, areg[i].z, areg[i].w};
                uint32_t p[4];
                #pragma unroll
                for (int j = 0; j < 4; j++) {
                    __nv_bfloat16 hi = __float2bfloat16_rn(xs[j]);
                    __nv_bfloat16 lo = __float2bfloat16_rn(xs[j] - __bfloat162float(hi));
                    __nv_bfloat162 pr; pr.x = hi; pr.y = lo;
                    p[j] = *(uint32_t*)&pr;
                }
                *(uint4*)(sm8 + buf * 8192 + off) = *(uint4*)p;
            }
            // B pass0: (hi, hi); pass1: (lo, lo)
            {
                float xs[4] = {breg[i].x, breg[i].y, breg[i].z, breg[i].w};
                uint32_t p0[4], p1[4];
                #pragma unroll
                for (int j = 0; j < 4; j++) {
                    __nv_bfloat16 hi = __float2bfloat16_rn(xs[j]);
                    __nv_bfloat16 lo = __float2bfloat16_rn(xs[j] - __bfloat162float(hi));
                    __nv_bfloat162 q0; q0.x = hi; q0.y = hi;
                    __nv_bfloat162 q1; q1.x = lo; q1.y = lo;
                    p0[j] = *(uint32_t*)&q0;
                    p1[j] = *(uint32_t*)&q1;
                }
                *(uint4*)(sm8 + 16384 + buf * 8192 + off) = *(uint4*)p0;
                *(uint4*)(sm8 + 32768 + buf * 8192 + off) = *(uint4*)p1;
            }
        }
    };

    ldAB(0); stAB(0);
    ldAB(1);
    for (int t = 0; t < 65; t++) {
        const int buf = t & 1;
        if (t < 64) {
            stAB(buf ^ 1);
            if (t + 2 <= 64) ldAB(t + 2);
        }
        __syncthreads();
        const uint32_t sbl = smem_u32(sm8);
        const uint32_t ab = sbl + buf * 8192;
        const uint32_t b0b = sbl + 16384 + buf * 8192;
        const uint32_t b1b = sbl + 32768 + buf * 8192;
        #pragma unroll
        for (int ks = 0; ks < 4; ks++) {
            uint32_t a[4];
            uint32_t byte = (uint32_t)((wm + (lane & 15)) * 128 + (lane >> 4) * 16 + ks * 32);
            LDSM_X4(a[0], a[1], a[2], a[3], ab + SWZ(byte));
            uint32_t b0[4][2], b1[4][2];
            #pragma unroll
            for (int nr = 0; nr < 2; nr++) {
                uint32_t by2 = (uint32_t)((wn + nr * 16 + (lane & 15)) * 128
                                          + (lane >> 4) * 16 + ks * 32);
                uint32_t r0, r1, r2, r3;
                LDSM_X4(r0, r1, r2, r3, b0b + SWZ(by2));
                b0[nr * 2][0] = r0; b0[nr * 2][1] = r2;
                b0[nr * 2 + 1][0] = r1; b0[nr * 2 + 1][1] = r3;
                LDSM_X4(r0, r1, r2, r3, b1b + SWZ(by2));
                b1[nr * 2][0] = r0; b1[nr * 2][1] = r2;
                b1[nr * 2 + 1][0] = r1; b1[nr * 2 + 1][1] = r3;
            }
            #pragma unroll
            for (int nt = 0; nt < 4; nt++) {
                MMA16816(d[nt], a, b0[nt]);
                MMA16816(d[nt], a, b1[nt]);
            }
        }
        __syncthreads();
    }

    #pragma unroll
    for (int half = 0; half < 2; half++) {
        int row = bm + wm + half * 8 + (lane >> 2);
        #pragma unroll
        for (int nt = 0; nt < 4; nt++) {
            int n = bn + wn + nt * 8 + (lane & 3) * 2;
            float bias0 = (n < 64) ? bb1[n] : bh1[n - 64];
            float bias1 = (n + 1 < 64) ? bb1[n + 1] : bh1[n + 1 - 64];
            float v0 = fmaxf(d[nt][half * 2 + 0] + bias0, 0.f);
            float v1 = fmaxf(d[nt][half * 2 + 1] + bias1, 0.f);
            *(float2*)&g_hid[row * 192 + n] = make_float2(v0, v1);
        }
    }
}

// =====================================================================
// K4: attention, 2 batches/CTA; logits via tensor core; staged epilogue
// =====================================================================
__global__ __launch_bounds__(256, 2) void k_attn(const float* __restrict__ obs,
                                                 const float* __restrict__ Wb2,
                                                 const float* __restrict__ bb2,
                                                 const float* __restrict__ Wh2,
                                                 const float* __restrict__ bh2) {
    __shared__ float ent2[2 * 2048];
    __shared__ float u2[2 * 512];
    __shared__ float vms2[2 * 256];
    __shared__ float tv2[2 * 128];
    __shared__ float whl2[2 * 8];
    __shared__ __align__(128) __nv_bfloat16 Wvs[128 * 64];

    const int tid = threadIdx.x;
    const int b0 = blockIdx.x * 2;
    const int lt = tid & 127, jb = tid >> 7;
    char* WvsB = (char*)Wvs;

    {
        const float4* src4 = (const float4*)(obs + (size_t)(b0 + jb) * IN + 4);
        float4* dst4 = (float4*)(ent2 + jb * 2048);
        #pragma unroll
        for (int i = lt; i < 508; i += 128) dst4[i] = src4[i];
        if (lt < 16) ent2[jb * 2048 + 2032 + lt] = 0.f;
    }
    {
        const uint4* wsrc = (const uint4*)g_Wvbf;
        #pragma unroll
        for (int i = tid; i < 1024; i += 256) {
            int row = i >> 3, c = i & 7;
            *(uint4*)(WvsB + SWZ((uint32_t)(row * 128 + c * 16))) = wsrc[i];
        }
    }
    vms2[jb * 256 + lt] = g_vm[(b0 + jb) * 256 + lt];
    vms2[jb * 256 + ((lt + 128) & 255)] = g_vm[(b0 + jb) * 256 + ((lt + 128) & 255)];

    {
        int b = b0 + jb;
        tv2[jb * 128 + lt] = ((lt < 64) ? g_te : g_ta)[b * 64 + (lt & 63)];
        int wl = lt >> 5, lane = lt & 31;
        float t = g_q[b * 256 + wl * 64 + lane]      * g_km[b * 256 + wl * 64 + lane]
                + g_q[b * 256 + wl * 64 + 32 + lane] * g_km[b * 256 + wl * 64 + 32 + lane];
        #pragma unroll
        for (int o = 16; o; o >>= 1) t += __shfl_xor_sync(0xffffffffu, t, o);
        if (lane == 0) whl2[jb * 8 + 4 + wl] = t * 0.125f;
        const float* hrow = g_hid + b * 192;
        float s = 0.f;
        #pragma unroll
        for (int j = lane; j < 128; j += 32) s += hrow[64 + j] * Wh2[wl * 128 + j];
        #pragma unroll
        for (int o = 16; o; o >>= 1) s += __shfl_xor_sync(0xffffffffu, s, o);
        if (lane == 0) whl2[jb * 8 + wl] = fabsf(s + bh2[wl]);
        if (wl == 0) {
            float bsum = hrow[lane] * Wb2[lane] + hrow[32 + lane] * Wb2[32 + lane];
            #pragma unroll
            for (int o = 16; o; o >>= 1) bsum += __shfl_xor_sync(0xffffffffu, bsum, o);
            if (lane == 0) g_bt[b] = bsum + bb2[0];
        }
    }
    __syncthreads();

    const int w = tid >> 5, lane = tid & 31;
    const int sel = w >> 2;
    const int mbase = w * 16;
    const int r = mbase + (lane >> 2);
    const int c0 = (lane & 3) * 2;

    float2 eA[2], eB[2], eC[2], eD[2];
    #pragma unroll
    for (int j = 0; j < 2; j++) {
        const float* ent = ent2 + j * 2048;
        eA[j] = *(float2*)&ent[r * 16 + c0];
        eB[j] = *(float2*)&ent[r * 16 + c0 + 8];
        eC[j] = *(float2*)&ent[(r + 8) * 16 + c0];
        eD[j] = *(float2*)&ent[(r + 8) * 16 + c0 + 8];
    }

    // ---- logits via mma
    {
        int hB = lane >> 2;
        #pragma unroll
        for (int j = 0; j < 2; j++) {
            uint32_t a[4];
            a[0] = packbf2(eA[j].x, eA[j].y);
            a[1] = packbf2(eC[j].x, eC[j].y);
            a[2] = packbf2(eB[j].x, eB[j].y);
            a[3] = packbf2(eD[j].x, eD[j].y);
            uint32_t bfrag[2] = {0u, 0u};
            if (hB < 4) {
                const float* tvb = tv2 + j * 128 + sel * 64 + hB * 16;
                bfrag[0] = packbf2(tvb[c0], tvb[c0 + 1]);
                bfrag[1] = packbf2(tvb[c0 + 8], tvb[c0 + 9]);
            }
            float dl[4] = {0.f, 0.f, 0.f, 0.f};
            MMA16816(dl, a, bfrag);
            float* u = u2 + j * 512;
            if (c0 < 4) {
                if (r < 127) {
                    u[c0 * 128 + 1 + r] = dl[0];
                    u[(c0 + 1) * 128 + 1 + r] = dl[1];
                }
                if (r + 8 < 127) {
                    u[c0 * 128 + 9 + r] = dl[2];
                    u[(c0 + 1) * 128 + 9 + r] = dl[3];
                }
            }
        }
        if (lt < 4) u2[jb * 512 + lt * 128] = whl2[jb * 8 + 4 + lt];
    }
    __syncthreads();

    // ---- softmax
    {
        float* u = u2 + jb * 512;
        int h = lt >> 5, lane2 = lt & 31;
        float v0[4], m0 = -3.4e38f;
        #pragma unroll
        for (int j = 0; j < 4; j++) { v0[j] = u[h * 128 + lane2 + 32 * j]; m0 = fmaxf(m0, v0[j]); }
        #pragma unroll
        for (int o = 16; o; o >>= 1) m0 = fmaxf(m0, __shfl_xor_sync(0xffffffffu, m0, o));
        float ss = 0.f;
        #pragma unroll
        for (int j = 0; j < 4; j++) { v0[j] = expf(v0[j] - m0); ss += v0[j]; }
        #pragma unroll
        for (int o = 16; o; o >>= 1) ss += __shfl_xor_sync(0xffffffffu, ss, o);
        float sc = whl2[jb * 8 + h] / ss;
        #pragma unroll
        for (int j = 0; j < 4; j++) u[h * 128 + lane2 + 32 * j] = v0[j] * sc;
    }
    __syncthreads();

    // ---- tensor-core mix + staged coalesced epilogue
    {
        uint32_t wb = smem_u32(Wvs) + (uint32_t)sel * 8192u;

        float d[2][8][4] = {};
        #pragma unroll
        for (int ks = 0; ks < 4; ks++) {
            uint32_t bfr[8][2];
            #pragma unroll
            for (int nr = 0; nr < 4; nr++) {
                uint32_t byte2 = (uint32_t)((nr * 16 + (lane & 15)) * 128 + (lane >> 4) * 16 + ks * 32);
                uint32_t r0, r1, r2, r3;
                LDSM_X4(r0, r1, r2, r3, wb + SWZ(byte2));
                bfr[nr * 2 + 0][0] = r0; bfr[nr * 2 + 0][1] = r2;
                bfr[nr * 2 + 1][0] = r1; bfr[nr * 2 + 1][1] = r3;
            }
            #pragma unroll
            for (int j = 0; j < 2; j++) {
                const float* u = u2 + j * 512;
                float ul = (r < 127)     ? u[ks * 128 + r + 1] : 0.f;
                float uh = (r + 8 < 127) ? u[ks * 128 + r + 9] : 0.f;
                uint32_t a[4];
                a[0] = packbf2(ul * eA[j].x, ul * eA[j].y);
                a[1] = packbf2(uh * eC[j].x, uh * eC[j].y);
                a[2] = packbf2(ul * eB[j].x, ul * eB[j].y);
                a[3] = packbf2(uh * eD[j].x, uh * eD[j].y);
                #pragma unroll
                for (int nt = 0; nt < 8; nt++) MMA16816(d[j][nt], a, bfr[nt]);
            }
        }

        char* stg = (char*)ent2;
        #pragma unroll
        for (int j = 0; j < 2; j++) {
            __syncthreads();
            if (tid < 64) {
                const float* u = u2 + j * 512;
                const float* vms = vms2 + j * 256;
                float s = 0.f;
                #pragma unroll
                for (int h = 0; h < 4; h++) s += u[h * 128] * vms[h * 64 + tid];
                *(__nv_bfloat16*)(stg + SWZ((uint32_t)(tid * 2))) = __float2bfloat16_rn(s);
            }
            #pragma unroll
            for (int half = 0; half < 2; half++) {
                int Arow = mbase + half * 8 + (lane >> 2);
                if (Arow < 127) {
                    int na = Arow + 1;
                    #pragma unroll
                    for (int nt = 0; nt < 8; nt++) {
                        int e = nt * 8 + (lane & 3) * 2;
                        *(uint32_t*)(stg + SWZ((uint32_t)(na * 128 + e * 2))) =
                            packbf2(d[j][nt][half * 2 + 0], d[j][nt][half * 2 + 1]);
                    }
                }
            }
            __syncthreads();
            uint4* dst = (uint4*)(g_Abf + (size_t)(b0 + j) * KTOT);
            #pragma unroll
            for (int i = tid; i < 1024; i += 256)
                dst[i] = *(uint4*)(stg + SWZ((uint32_t)(i * 16)));
        }
    }
}

// =====================================================================
// K5: bf16 mma GEMM, CTA tile 64x256 (N un-tiled), split-K x4,
//     warp tile 32x64, 2-stage pipeline, 2 CTAs/SM
// =====================================================================
__global__ __launch_bounds__(256, 2) void k_final_mma() {
    extern __shared__ __align__(128) char smf[];
    const uint32_t sb = smem_u32(smf);
    const int tid = threadIdx.x, lane = tid & 31, w = tid >> 5;
    const int bm = blockIdx.x * 64;
    const int kz = blockIdx.y;
    const int tbase = kz * 32;
    const int wm = (w & 1) * 32, wn = (w >> 1) * 64;
    float* part = g_part + (size_t)kz * BS * RNN;

    float d[2][8][4] = {};

    auto loadChunk = [&](int t, int s) {
        const __nv_bfloat16* Asrc = g_Abf + (size_t)bm * KTOT + (size_t)(tbase + t) * 64;
        #pragma unroll
        for (int i = 0; i < 2; i++) {
            int idx = tid + 256 * i;
            int row = idx >> 3, c = idx & 7;
            cp16(sb + s * 8192 + SWZ((uint32_t)(row * 128 + c * 16)),
                 Asrc + (size_t)row * KTOT + c * 8);
        }
        const __nv_bfloat16* Bsrc = g_Wfbf + (size_t)(tbase + t) * 64;
        #pragma unroll
        for (int i = 0; i < 8; i++) {
            int idx = tid + 256 * i;
            int row = idx >> 3, c = idx & 7;
            cp16(sb + 16384 + s * 32768 + SWZ((uint32_t)(row * 128 + c * 16)),
                 Bsrc + (size_t)row * KTOT + c * 8);
        }
        CP_COMMIT();
    };

    loadChunk(0, 0);
    for (int t = 0; t < 32; t++) {
        const int s = t & 1;
        if (t + 1 < 32) { loadChunk(t + 1, s ^ 1); CP_WAIT(1); }
        else            { CP_WAIT(0); }
        __syncthreads();

        const uint32_t abase = sb + s * 8192;
        const uint32_t bbase = sb + 16384 + s * 32768;
        #pragma unroll
        for (int ks = 0; ks < 4; ks++) {
            uint32_t a[2][4], b[8][2];
            #pragma unroll
            for (int mt = 0; mt < 2; mt++) {
                uint32_t byte = (uint32_t)((wm + mt * 16 + (lane & 15)) * 128
                                           + (lane >> 4) * 16 + ks * 32);
                LDSM_X4(a[mt][0], a[mt][1], a[mt][2], a[mt][3], abase + SWZ(byte));
            }
            #pragma unroll
            for (int nr = 0; nr < 4; nr++) {
                uint32_t byte = (uint32_t)((wn + nr * 16 + (lane & 15)) * 128
                                           + (lane >> 4) * 16 + ks * 32);
                uint32_t r0, r1, r2, r3;
                LDSM_X4(r0, r1, r2, r3, bbase + SWZ(byte));
                b[nr * 2 + 0][0] = r0; b[nr * 2 + 0][1] = r2;
                b[nr * 2 + 1][0] = r1; b[nr * 2 + 1][1] = r3;
            }
            #pragma unroll
            for (int mt = 0; mt < 2; mt++)
                #pragma unroll
                for (int nt = 0; nt < 8; nt++)
                    MMA16816(d[mt][nt], a[mt], b[nt]);
        }
        __syncthreads();
    }

    const int nbase = wn + (lane & 3) * 2;
    #pragma unroll
    for (int mt = 0; mt < 2; mt++) {
        #pragma unroll
        for (int half = 0; half < 2; half++) {
            int row = bm + wm + mt * 16 + half * 8 + (lane >> 2);
            #pragma unroll
            for (int nt = 0; nt < 8; nt++) {
                int col = nbase + nt * 8;
                *(float2*)&part[(size_t)row * RNN + col] =
                    make_float2(d[mt][nt][half * 2 + 0], d[mt][nt][half * 2 + 1]);
            }
        }
    }
}

// =====================================================================
// K6: out = sum(parts) + bt*S + bf
// =====================================================================
__global__ __launch_bounds__(256) void k_out(const float* __restrict__ bfv,
                                             float* __restrict__ out) {
    int i = blockIdx.x * 256 + threadIdx.x;
    int row = i >> 6;
    int col4 = (i & 63) * 4;
    const size_t stride4 = (size_t)BS * RNN / 4;
    float4 p0 = ((const float4*)g_part)[i];
    float4 p1 = ((const float4*)g_part)[i + stride4];
    float4 p2 = ((const float4*)g_part)[i + 2 * stride4];
    float4 p3 = ((const float4*)g_part)[i + 3 * stride4];
    float4 sv = *(const float4*)&g_S[col4];
    float4 bv = *(const float4*)&bfv[col4];
    float bt = g_bt[row];
    float4 o;
    o.x = (p0.x + p1.x) + (p2.x + p3.x) + bt * sv.x + bv.x;
    o.y = (p0.y + p1.y) + (p2.y + p3.y) + bt * sv.y + bv.y;
    o.z = (p0.z + p1.z) + (p2.z + p3.z) + bt * sv.z + bv.z;
    o.w = (p0.w + p1.w) + (p2.w + p3.w) + bt * sv.w + bv.w;
    ((float4*)out)[i] = o;
}

// =====================================================================
// launch
// =====================================================================
extern "C" void kernel_launch(void* const* d_in, const int* in_sizes, int n_in,
                              void* d_out, int out_size) {
    const float* obs  = (const float*)d_in[0];
    const float* Wq1  = (const float*)d_in[1];
    const float* bq1  = (const float*)d_in[2];
    const float* Wq2  = (const float*)d_in[3];
    const float* Wkm1 = (const float*)d_in[4];
    const float* bkm1 = (const float*)d_in[5];
    const float* Wkm2 = (const float*)d_in[6];
    const float* Wke  = (const float*)d_in[7];
    const float* Wka  = (const float*)d_in[8];
    const float* Wvm1 = (const float*)d_in[9];
    const float* bvm1 = (const float*)d_in[10];
    const float* Wvm2 = (const float*)d_in[11];
    const float* Wve  = (const float*)d_in[12];
    const float* Wva  = (const float*)d_in[13];
    const float* Wb1  = (const float*)d_in[14];
    const float* bb1  = (const float*)d_in[15];
    const float* Wb2  = (const float*)d_in[16];
    const float* bb2  = (const float*)d_in[17];
    const float* Wh1  = (const float*)d_in[18];
    const float* bh1  = (const float*)d_in[19];
    const float* Wh2  = (const float*)d_in[20];
    const float* bh2  = (const float*)d_in[21];
    const float* Wf   = (const float*)d_in[22];
    const float* bf   = (const float*)d_in[23];
    float* out = (float*)d_out;

    const int pm_smem = 75264;
    const int final_smem = 16384 + 2 * 32768;   // 81920
    cudaFuncSetAttribute(k_prep_mlp, cudaFuncAttributeMaxDynamicSharedMemorySize, pm_smem);
    cudaFuncSetAttribute(k_final_mma, cudaFuncAttributeMaxDynamicSharedMemorySize, final_smem);

    k_prep_mlp<<<384, 256, pm_smem>>>(obs, Wq1, bq1, Wq2, Wkm1, bkm1, Wkm2,
                                      Wvm1, bvm1, Wvm2, Wke, Wka);
    k_front_tc<<<449, 256>>>(obs, bb1, bh1, Wb1, Wh1, Wf, Wve, Wva);
    k_attn<<<2048, 256>>>(obs, Wb2, bb2, Wh2, bh2);
    k_final_mma<<<dim3(64, 4), 256, final_smem>>>();
    k_out<<<1024, 256>>>(bf, out);
}

// round 17
// speedup vs baseline: 1.0939x; 1.0939x over previous
#include <cuda_runtime.h>
#include <cuda_bf16.h>
#include <cstdint>
#include <cstddef>

// ---------------- problem dims ----------------
#define BS 4096
#define IN 2056
#define MF 24
#define H 4
#define HE 128
#define E 64
#define NA 128
#define RNN 256
#define KTOT 8192

// ---------------- scratch ----------------
__device__ float g_hid[BS * 192];
__device__ float g_bt[BS];
__device__ float g_q[BS * H * E];
__device__ float g_km[BS * H * E];
__device__ float g_vm[BS * H * E];
__device__ float g_te[BS * 64];
__device__ float g_ta[BS * 64];
__device__ float g_S[RNN];
__device__ float g_part[(size_t)4 * BS * RNN];
__device__ __align__(16) __nv_bfloat16 g_Abf[(size_t)BS * KTOT];
__device__ __align__(16) __nv_bfloat16 g_Wfbf[(size_t)RNN * KTOT];
__device__ __align__(16) __nv_bfloat16 g_Wvbf[2 * 64 * 64];

// ---------------- PTX helpers ----------------
__device__ __forceinline__ uint32_t smem_u32(const void* p) {
    uint32_t a;
    asm("{ .reg .u64 t; cvta.to.shared.u64 t, %1; cvt.u32.u64 %0, t; }" : "=r"(a) : "l"(p));
    return a;
}
__device__ __forceinline__ void cp16(uint32_t dst, const void* src) {
    asm volatile("cp.async.cg.shared.global [%0], [%1], 16;" :: "r"(dst), "l"(src) : "memory");
}
#define CP_COMMIT() asm volatile("cp.async.commit_group;" ::: "memory")
#define CP_WAIT(n)  asm volatile("cp.async.wait_group %0;" :: "n"(n) : "memory")

#define LDSM_X4(r0, r1, r2, r3, addr) \
    asm volatile("ldmatrix.sync.aligned.m8n8.x4.shared.b16 {%0,%1,%2,%3}, [%4];" \
                 : "=r"(r0), "=r"(r1), "=r"(r2), "=r"(r3) : "r"(addr))

#define MMA16816(d, a, b) \
    asm volatile("mma.sync.aligned.m16n8k16.row.col.f32.bf16.bf16.f32 " \
                 "{%0,%1,%2,%3}, {%4,%5,%6,%7}, {%8,%9}, {%0,%1,%2,%3};" \
                 : "+f"((d)[0]), "+f"((d)[1]), "+f"((d)[2]), "+f"((d)[3]) \
                 : "r"((a)[0]), "r"((a)[1]), "r"((a)[2]), "r"((a)[3]), \
                   "r"((b)[0]), "r"((b)[1]))

#define SWZ(x) ((x) ^ (((x) >> 3) & 0x70))

__device__ __forceinline__ uint32_t packbf2(float x, float y) {
    __nv_bfloat162 p = __floats2bfloat162_rn(x, y);
    return *(uint32_t*)&p;
}

// =====================================================================
// K0 "mega": ALL independent front-end work in one launch.
//   blocks 0..191   : front GEMM (split-bf16 exact, in-register cvt)
//   blocks 192..575 : m-MLPs; mlp==0 also te/ta via mma
//   blocks 576..831 : Wf row -> permuted bf16 + S[r]
//   block 832       : Wv flatten
// =====================================================================
__global__ __launch_bounds__(256) void k_mega(
        const float* __restrict__ obs,
        const float* __restrict__ bb1, const float* __restrict__ bh1,
        const float* __restrict__ Wb1, const float* __restrict__ Wh1,
        const float* __restrict__ Wf,
        const float* __restrict__ Wve, const float* __restrict__ Wva,
        const float* __restrict__ Wq1, const float* __restrict__ bq1,
        const float* __restrict__ Wq2,
        const float* __restrict__ Wkm1, const float* __restrict__ bkm1,
        const float* __restrict__ Wkm2,
        const float* __restrict__ Wvm1, const float* __restrict__ bvm1,
        const float* __restrict__ Wvm2,
        const float* __restrict__ Wke, const float* __restrict__ Wka) {
    extern __shared__ __align__(128) char smp[];
    const int blk = blockIdx.x;
    const int tid = threadIdx.x;

    if (blk < 192) {
        // ============== front GEMM ==============
        const int lane = tid & 31, w = tid >> 5;
        const int bm = (blk & 63) * 64, bn = (blk >> 6) * 64;
        const int wm = (w & 3) * 16, wn = (w >> 2) * 32;
        float d[4][4] = {};

        const int row0 = tid >> 3, c16_0 = tid & 7;
        const int row1 = (tid + 256) >> 3, c16_1 = (tid + 256) & 7;
        const float* Wr0 = (bn + row0 < 64) ? (Wb1 + (size_t)(bn + row0) * IN)
                                            : (Wh1 + (size_t)(bn + row0 - 64) * IN);
        const float* Wr1 = (bn + row1 < 64) ? (Wb1 + (size_t)(bn + row1) * IN)
                                            : (Wh1 + (size_t)(bn + row1 - 64) * IN);
        float4 areg[2], breg[2];

        auto ldAB = [&](int t) {
            int k0 = t * 32 + c16_0 * 4;
            int k1 = t * 32 + c16_1 * 4;
            float4 z = make_float4(0.f, 0.f, 0.f, 0.f);
            areg[0] = (k0 < IN) ? *(const float4*)(obs + (size_t)(bm + row0) * IN + k0) : z;
            areg[1] = (k1 < IN) ? *(const float4*)(obs + (size_t)(bm + row1) * IN + k1) : z;
            breg[0] = (k0 < IN) ? *(const float4*)(Wr0 + k0) : z;
            breg[1] = (k1 < IN) ? *(const float4*)(Wr1 + k1) : z;
        };
        auto stAB = [&](int buf) {
            #pragma unroll
            for (int i = 0; i < 2; i++) {
                int row = i ? row1 : row0, c16 = i ? c16_1 : c16_0;
                uint32_t off = SWZ((uint32_t)(row * 128 + c16 * 16));
                {
                    float xs[4] = {areg[i].x, areg[i].y, areg[i].z, areg[i].w};
                    uint32_t p[4];
                    #pragma unroll
                    for (int j = 0; j < 4; j++) {
                        __nv_bfloat16 hi = __float2bfloat16_rn(xs[j]);
                        __nv_bfloat16 lo = __float2bfloat16_rn(xs[j] - __bfloat162float(hi));
                        __nv_bfloat162 pr; pr.x = hi; pr.y = lo;
                        p[j] = *(uint32_t*)&pr;
                    }
                    *(uint4*)(smp + buf * 8192 + off) = *(uint4*)p;
                }
                {
                    float xs[4] = {breg[i].x, breg[i].y, breg[i].z, breg[i].w};
                    uint32_t p0[4], p1[4];
                    #pragma unroll
                    for (int j = 0; j < 4; j++) {
                        __nv_bfloat16 hi = __float2bfloat16_rn(xs[j]);
                        __nv_bfloat16 lo = __float2bfloat16_rn(xs[j] - __bfloat162float(hi));
                        __nv_bfloat162 q0; q0.x = hi; q0.y = hi;
                        __nv_bfloat162 q1; q1.x = lo; q1.y = lo;
                        p0[j] = *(uint32_t*)&q0;
                        p1[j] = *(uint32_t*)&q1;
                    }
                    *(uint4*)(smp + 16384 + buf * 8192 + off) = *(uint4*)p0;
                    *(uint4*)(smp + 32768 + buf * 8192 + off) = *(uint4*)p1;
                }
            }
        };

        ldAB(0); stAB(0);
        ldAB(1);
        for (int t = 0; t < 65; t++) {
            const int buf = t & 1;
            if (t < 64) {
                stAB(buf ^ 1);
                if (t + 2 <= 64) ldAB(t + 2);
            }
            __syncthreads();
            const uint32_t sbl = smem_u32(smp);
            const uint32_t ab = sbl + buf * 8192;
            const uint32_t b0b = sbl + 16384 + buf * 8192;
            const uint32_t b1b = sbl + 32768 + buf * 8192;
            #pragma unroll
            for (int ks = 0; ks < 4; ks++) {
                uint32_t a[4];
                uint32_t byte = (uint32_t)((wm + (lane & 15)) * 128 + (lane >> 4) * 16 + ks * 32);
                LDSM_X4(a[0], a[1], a[2], a[3], ab + SWZ(byte));
                uint32_t b0[4][2], b1[4][2];
                #pragma unroll
                for (int nr = 0; nr < 2; nr++) {
                    uint32_t by2 = (uint32_t)((wn + nr * 16 + (lane & 15)) * 128
                                              + (lane >> 4) * 16 + ks * 32);
                    uint32_t r0, r1, r2, r3;
                    LDSM_X4(r0, r1, r2, r3, b0b + SWZ(by2));
                    b0[nr * 2][0] = r0; b0[nr * 2][1] = r2;
                    b0[nr * 2 + 1][0] = r1; b0[nr * 2 + 1][1] = r3;
                    LDSM_X4(r0, r1, r2, r3, b1b + SWZ(by2));
                    b1[nr * 2][0] = r0; b1[nr * 2][1] = r2;
                    b1[nr * 2 + 1][0] = r1; b1[nr * 2 + 1][1] = r3;
                }
                #pragma unroll
                for (int nt = 0; nt < 4; nt++) {
                    MMA16816(d[nt], a, b0[nt]);
                    MMA16816(d[nt], a, b1[nt]);
                }
            }
            __syncthreads();
        }

        #pragma unroll
        for (int half = 0; half < 2; half++) {
            int row = bm + wm + half * 8 + (lane >> 2);
            #pragma unroll
            for (int nt = 0; nt < 4; nt++) {
                int n = bn + wn + nt * 8 + (lane & 3) * 2;
                float bias0 = (n < 64) ? bb1[n] : bh1[n - 64];
                float bias1 = (n + 1 < 64) ? bb1[n + 1] : bh1[n + 1 - 64];
                float v0 = fmaxf(d[nt][half * 2 + 0] + bias0, 0.f);
                float v1 = fmaxf(d[nt][half * 2 + 1] + bias1, 0.f);
                *(float2*)&g_hid[row * 192 + n] = make_float2(v0, v1);
            }
        }
        return;
    }

    if (blk >= 576) {
        if (blk < 832) {
            // ============== Wf permute + S ==============
            int r = blk - 576;
            float* row = (float*)smp;
            float* red = (float*)smp + 8256;
            float s = 0.f;
            for (int i = tid; i < 8192; i += 256) {
                float v = Wf[(size_t)r * 8192 + i];
                row[i + (i >> 7)] = v;
                s += v;
            }
            #pragma unroll
            for (int o = 16; o; o >>= 1) s += __shfl_xor_sync(0xffffffffu, s, o);
            if ((tid & 31) == 0) red[tid >> 5] = s;
            __syncthreads();
            if (tid == 0) {
                float t = 0.f;
                #pragma unroll
                for (int j = 0; j < 8; j++) t += red[j];
                g_S[r] = t;
            }
            for (int i = tid; i < 8192; i += 256) {
                int na = i >> 6, e = i & 63;
                int src = e * 128 + na;
                g_Wfbf[(size_t)r * 8192 + i] = __float2bfloat16_rn(row[src + (src >> 7)]);
            }
        } else {
            // ============== Wv flatten ==============
            for (int i = tid; i < 8192; i += 256) {
                int sel = i >> 12, j = i & 4095;
                int e = j >> 6, hd = j & 63, h = hd >> 4, d = hd & 15;
                const float* W = sel ? Wva : Wve;
                g_Wvbf[i] = __float2bfloat16_rn(W[h * 1024 + e * 16 + d]);
            }
        }
        return;
    }

    // ============== m-MLP ==============
    {
        int idx = blk - 192;
        const int bm = (idx & 31) * 128;
        int yy = idx >> 5;
        const int mlp = yy >> 2, h = yy & 3;
        const int lane = tid & 31;

        float* msm = (float*)smp;
        float* w1s = (float*)(smp + 12800);
        float* b1s = (float*)(smp + 25600);
        char* h1B = smp + 26112;
        char* w2B = smp + 58880;

        const float* W1 = ((mlp == 0) ? Wq1 : (mlp == 1) ? Wkm1 : Wvm1) + h * HE * MF;
        const float* B1 = ((mlp == 0) ? bq1 : (mlp == 1) ? bkm1 : bvm1) + h * HE;
        const float* W2 = ((mlp == 0) ? Wq2 : (mlp == 1) ? Wkm2 : Wvm2) + h * E * HE;
        float* outp = (mlp == 0) ? g_q : (mlp == 1) ? g_km : g_vm;

        for (int i = tid; i < 128 * 24; i += 256) {
            int rr = i / 24, f = i - rr * 24;
            int col = (f < 4) ? f : (2032 + f);
            msm[rr * 25 + f] = obs[(size_t)(bm + rr) * IN + col];
        }
        for (int i = tid; i < 128 * 24; i += 256) {
            int g = i / 24, f = i - g * 24;
            w1s[g * 25 + f] = W1[g * 24 + f];
        }
        if (tid < 128) b1s[tid] = B1[tid];
        for (int i = tid; i < 1024; i += 256) {
            int e = i >> 4, g8 = (i & 15) * 8;
            int kk = g8 >> 6, wi = g8 & 63;
            const float* src = W2 + e * HE + g8;
            float4 v0 = *(const float4*)src;
            float4 v1 = *(const float4*)(src + 4);
            __nv_bfloat162 p[4];
            p[0] = __floats2bfloat162_rn(v0.x, v0.y);
            p[1] = __floats2bfloat162_rn(v0.z, v0.w);
            p[2] = __floats2bfloat162_rn(v1.x, v1.y);
            p[3] = __floats2bfloat162_rn(v1.z, v1.w);
            *(uint4*)(w2B + kk * 8192 + SWZ((uint32_t)(e * 128 + wi * 2))) = *(uint4*)p;
        }
        __syncthreads();

        {
            int rr = tid & 127, chalf = tid >> 7;
            float mreg[24];
            #pragma unroll
            for (int f = 0; f < 24; f++) mreg[f] = msm[rr * 25 + f];
            char* pan = h1B + chalf * 16384;
            #pragma unroll 4
            for (int c = 0; c < 64; c += 2) {
                int cc = chalf * 64 + c;
                float a0 = b1s[cc], a1 = b1s[cc + 1];
                const float* w0 = w1s + cc * 25;
                #pragma unroll
                for (int f = 0; f < 24; f++) {
                    a0 += mreg[f] * w0[f];
                    a1 += mreg[f] * w0[25 + f];
                }
                __nv_bfloat162 p = __floats2bfloat162_rn(fmaxf(a0, 0.f), fmaxf(a1, 0.f));
                *(__nv_bfloat162*)(pan + SWZ((uint32_t)(rr * 128 + c * 2))) = p;
            }
        }
        __syncthreads();

        {
            int w = tid >> 5;
            int wm = (w & 1) * 64, wn = (w >> 1) * 16;
            uint32_t h1b = smem_u32(h1B);
            uint32_t w2b = smem_u32(w2B);
            float d[4][2][4] = {};
            #pragma unroll
            for (int kk = 0; kk < 2; kk++) {
                uint32_t ab = h1b + kk * 16384;
                uint32_t bb = w2b + kk * 8192;
                #pragma unroll
                for (int ks = 0; ks < 4; ks++) {
                    uint32_t bfr[2][2];
                    {
                        uint32_t by = (uint32_t)((wn + (lane & 15)) * 128 + (lane >> 4) * 16 + ks * 32);
                        uint32_t r0, r1, r2, r3;
                        LDSM_X4(r0, r1, r2, r3, bb + SWZ(by));
                        bfr[0][0] = r0; bfr[0][1] = r2;
                        bfr[1][0] = r1; bfr[1][1] = r3;
                    }
                    #pragma unroll
                    for (int mt = 0; mt < 4; mt++) {
                        uint32_t a[4];
                        uint32_t by = (uint32_t)((wm + mt * 16 + (lane & 15)) * 128
                                                 + (lane >> 4) * 16 + ks * 32);
                        LDSM_X4(a[0], a[1], a[2], a[3], ab + SWZ(by));
                        MMA16816(d[mt][0], a, bfr[0]);
                        MMA16816(d[mt][1], a, bfr[1]);
                    }
                }
            }
            #pragma unroll
            for (int mt = 0; mt < 4; mt++)
                #pragma unroll
                for (int half = 0; half < 2; half++) {
                    int row = bm + wm + mt * 16 + half * 8 + (lane >> 2);
                    #pragma unroll
                    for (int nt = 0; nt < 2; nt++) {
                        int e = wn + nt * 8 + (lane & 3) * 2;
                        *(float2*)&outp[(size_t)row * 256 + h * 64 + e] =
                            make_float2(d[mt][nt][half * 2], d[mt][nt][half * 2 + 1]);
                    }
                }

            if (mlp == 0) {
                __syncthreads();
                char* qB = h1B;
                #pragma unroll
                for (int mt = 0; mt < 4; mt++)
                    #pragma unroll
                    for (int half = 0; half < 2; half++) {
                        int rl = wm + mt * 16 + half * 8 + (lane >> 2);
                        #pragma unroll
                        for (int nt = 0; nt < 2; nt++) {
                            int e = wn + nt * 8 + (lane & 3) * 2;
                            *(__nv_bfloat162*)(qB + SWZ((uint32_t)(rl * 128 + e * 2))) =
                                __floats2bfloat162_rn(d[mt][nt][half * 2], d[mt][nt][half * 2 + 1]);
                        }
                    }
                for (int i = tid; i < 2048; i += 256) {
                    int row = i >> 6, e = i & 63;
                    int dd = row & 15;
                    const float* Wk = (row < 16) ? Wke : Wka;
                    *(__nv_bfloat16*)(w2B + SWZ((uint32_t)(row * 128 + e * 2))) =
                        __float2bfloat16_rn(Wk[h * 1024 + e * 16 + dd]);
                }
                __syncthreads();
                int wm2 = w * 16;
                uint32_t ab2 = smem_u32(qB);
                uint32_t bb3 = smem_u32(w2B);
                float dd[4][4] = {};
                #pragma unroll
                for (int ks = 0; ks < 4; ks++) {
                    uint32_t a[4];
                    uint32_t by = (uint32_t)((wm2 + (lane & 15)) * 128 + (lane >> 4) * 16 + ks * 32);
                    LDSM_X4(a[0], a[1], a[2], a[3], ab2 + SWZ(by));
                    uint32_t bfr[4][2];
                    #pragma unroll
                    for (int nr = 0; nr < 2; nr++) {
                        uint32_t by2 = (uint32_t)((nr * 16 + (lane & 15)) * 128
                                                  + (lane >> 4) * 16 + ks * 32);
                        uint32_t r0, r1, r2, r3;
                        LDSM_X4(r0, r1, r2, r3, bb3 + SWZ(by2));
                        bfr[nr * 2][0] = r0; bfr[nr * 2][1] = r2;
                        bfr[nr * 2 + 1][0] = r1; bfr[nr * 2 + 1][1] = r3;
                    }
                    #pragma unroll
                    for (int nt = 0; nt < 4; nt++) MMA16816(dd[nt], a, bfr[nt]);
                }
                #pragma unroll
                for (int half = 0; half < 2; half++) {
                    int bglob = bm + wm2 + half * 8 + (lane >> 2);
                    #pragma unroll
                    for (int nt = 0; nt < 4; nt++) {
                        int n = nt * 8 + (lane & 3) * 2;
                        float v0 = dd[nt][half * 2] * 0.125f;
                        float v1 = dd[nt][half * 2 + 1] * 0.125f;
                        float* dst = (n < 16) ? (g_te + bglob * 64 + h * 16 + n)
                                              : (g_ta + bglob * 64 + h * 16 + (n - 16));
                        *(float2*)dst = make_float2(v0, v1);
                    }
                }
            }
        }
    }
}

// =====================================================================
// K4: attention, 2 batches/CTA; logits via tensor core; staged epilogue
// =====================================================================
__global__ __launch_bounds__(256, 2) void k_attn(const float* __restrict__ obs,
                                                 const float* __restrict__ Wb2,
                                                 const float* __restrict__ bb2,
                                                 const float* __restrict__ Wh2,
                                                 const float* __restrict__ bh2) {
    __shared__ float ent2[2 * 2048];
    __shared__ float u2[2 * 512];
    __shared__ float vms2[2 * 256];
    __shared__ float tv2[2 * 128];
    __shared__ float whl2[2 * 8];
    __shared__ __align__(128) __nv_bfloat16 Wvs[128 * 64];

    const int tid = threadIdx.x;
    const int b0 = blockIdx.x * 2;
    const int lt = tid & 127, jb = tid >> 7;
    char* WvsB = (char*)Wvs;

    {
        const float4* src4 = (const float4*)(obs + (size_t)(b0 + jb) * IN + 4);
        float4* dst4 = (float4*)(ent2 + jb * 2048);
        #pragma unroll
        for (int i = lt; i < 508; i += 128) dst4[i] = src4[i];
        if (lt < 16) ent2[jb * 2048 + 2032 + lt] = 0.f;
    }
    {
        const uint4* wsrc = (const uint4*)g_Wvbf;
        #pragma unroll
        for (int i = tid; i < 1024; i += 256) {
            int row = i >> 3, c = i & 7;
            *(uint4*)(WvsB + SWZ((uint32_t)(row * 128 + c * 16))) = wsrc[i];
        }
    }
    vms2[jb * 256 + lt] = g_vm[(b0 + jb) * 256 + lt];
    vms2[jb * 256 + ((lt + 128) & 255)] = g_vm[(b0 + jb) * 256 + ((lt + 128) & 255)];

    {
        int b = b0 + jb;
        tv2[jb * 128 + lt] = ((lt < 64) ? g_te : g_ta)[b * 64 + (lt & 63)];
        int wl = lt >> 5, lane = lt & 31;
        float t = g_q[b * 256 + wl * 64 + lane]      * g_km[b * 256 + wl * 64 + lane]
                + g_q[b * 256 + wl * 64 + 32 + lane] * g_km[b * 256 + wl * 64 + 32 + lane];
        #pragma unroll
        for (int o = 16; o; o >>= 1) t += __shfl_xor_sync(0xffffffffu, t, o);
        if (lane == 0) whl2[jb * 8 + 4 + wl] = t * 0.125f;
        const float* hrow = g_hid + b * 192;
        float s = 0.f;
        #pragma unroll
        for (int j = lane; j < 128; j += 32) s += hrow[64 + j] * Wh2[wl * 128 + j];
        #pragma unroll
        for (int o = 16; o; o >>= 1) s += __shfl_xor_sync(0xffffffffu, s, o);
        if (lane == 0) whl2[jb * 8 + wl] = fabsf(s + bh2[wl]);
        if (wl == 0) {
            float bsum = hrow[lane] * Wb2[lane] + hrow[32 + lane] * Wb2[32 + lane];
            #pragma unroll
            for (int o = 16; o; o >>= 1) bsum += __shfl_xor_sync(0xffffffffu, bsum, o);
            if (lane == 0) g_bt[b] = bsum + bb2[0];
        }
    }
    __syncthreads();

    const int w = tid >> 5, lane = tid & 31;
    const int sel = w >> 2;
    const int mbase = w * 16;
    const int r = mbase + (lane >> 2);
    const int c0 = (lane & 3) * 2;

    float2 eA[2], eB[2], eC[2], eD[2];
    #pragma unroll
    for (int j = 0; j < 2; j++) {
        const float* ent = ent2 + j * 2048;
        eA[j] = *(float2*)&ent[r * 16 + c0];
        eB[j] = *(float2*)&ent[r * 16 + c0 + 8];
        eC[j] = *(float2*)&ent[(r + 8) * 16 + c0];
        eD[j] = *(float2*)&ent[(r + 8) * 16 + c0 + 8];
    }

    // ---- logits via mma
    {
        int hB = lane >> 2;
        #pragma unroll
        for (int j = 0; j < 2; j++) {
            uint32_t a[4];
            a[0] = packbf2(eA[j].x, eA[j].y);
            a[1] = packbf2(eC[j].x, eC[j].y);
            a[2] = packbf2(eB[j].x, eB[j].y);
            a[3] = packbf2(eD[j].x, eD[j].y);
            uint32_t bfrag[2] = {0u, 0u};
            if (hB < 4) {
                const float* tvb = tv2 + j * 128 + sel * 64 + hB * 16;
                bfrag[0] = packbf2(tvb[c0], tvb[c0 + 1]);
                bfrag[1] = packbf2(tvb[c0 + 8], tvb[c0 + 9]);
            }
            float dl[4] = {0.f, 0.f, 0.f, 0.f};
            MMA16816(dl, a, bfrag);
            float* u = u2 + j * 512;
            if (c0 < 4) {
                if (r < 127) {
                    u[c0 * 128 + 1 + r] = dl[0];
                    u[(c0 + 1) * 128 + 1 + r] = dl[1];
                }
                if (r + 8 < 127) {
                    u[c0 * 128 + 9 + r] = dl[2];
                    u[(c0 + 1) * 128 + 9 + r] = dl[3];
                }
            }
        }
        if (lt < 4) u2[jb * 512 + lt * 128] = whl2[jb * 8 + 4 + lt];
    }
    __syncthreads();

    // ---- softmax
    {
        float* u = u2 + jb * 512;
        int h = lt >> 5, lane2 = lt & 31;
        float v0[4], m0 = -3.4e38f;
        #pragma unroll
        for (int j = 0; j < 4; j++) { v0[j] = u[h * 128 + lane2 + 32 * j]; m0 = fmaxf(m0, v0[j]); }
        #pragma unroll
        for (int o = 16; o; o >>= 1) m0 = fmaxf(m0, __shfl_xor_sync(0xffffffffu, m0, o));
        float ss = 0.f;
        #pragma unroll
        for (int j = 0; j < 4; j++) { v0[j] = expf(v0[j] - m0); ss += v0[j]; }
        #pragma unroll
        for (int o = 16; o; o >>= 1) ss += __shfl_xor_sync(0xffffffffu, ss, o);
        float sc = whl2[jb * 8 + h] / ss;
        #pragma unroll
        for (int j = 0; j < 4; j++) u[h * 128 + lane2 + 32 * j] = v0[j] * sc;
    }
    __syncthreads();

    // ---- tensor-core mix + staged coalesced epilogue
    {
        uint32_t wb = smem_u32(Wvs) + (uint32_t)sel * 8192u;

        float d[2][8][4] = {};
        #pragma unroll
        for (int ks = 0; ks < 4; ks++) {
            uint32_t bfr[8][2];
            #pragma unroll
            for (int nr = 0; nr < 4; nr++) {
                uint32_t byte2 = (uint32_t)((nr * 16 + (lane & 15)) * 128 + (lane >> 4) * 16 + ks * 32);
                uint32_t r0, r1, r2, r3;
                LDSM_X4(r0, r1, r2, r3, wb + SWZ(byte2));
                bfr[nr * 2 + 0][0] = r0; bfr[nr * 2 + 0][1] = r2;
                bfr[nr * 2 + 1][0] = r1; bfr[nr * 2 + 1][1] = r3;
            }
            #pragma unroll
            for (int j = 0; j < 2; j++) {
                const float* u = u2 + j * 512;
                float ul = (r < 127)     ? u[ks * 128 + r + 1] : 0.f;
                float uh = (r + 8 < 127) ? u[ks * 128 + r + 9] : 0.f;
                uint32_t a[4];
                a[0] = packbf2(ul * eA[j].x, ul * eA[j].y);
                a[1] = packbf2(uh * eC[j].x, uh * eC[j].y);
                a[2] = packbf2(ul * eB[j].x, ul * eB[j].y);
                a[3] = packbf2(uh * eD[j].x, uh * eD[j].y);
                #pragma unroll
                for (int nt = 0; nt < 8; nt++) MMA16816(d[j][nt], a, bfr[nt]);
            }
        }

        char* stg = (char*)ent2;
        #pragma unroll
        for (int j = 0; j < 2; j++) {
            __syncthreads();
            if (tid < 64) {
                const float* u = u2 + j * 512;
                const float* vms = vms2 + j * 256;
                float s = 0.f;
                #pragma unroll
                for (int h = 0; h < 4; h++) s += u[h * 128] * vms[h * 64 + tid];
                *(__nv_bfloat16*)(stg + SWZ((uint32_t)(tid * 2))) = __float2bfloat16_rn(s);
            }
            #pragma unroll
            for (int half = 0; half < 2; half++) {
                int Arow = mbase + half * 8 + (lane >> 2);
                if (Arow < 127) {
                    int na = Arow + 1;
                    #pragma unroll
                    for (int nt = 0; nt < 8; nt++) {
                        int e = nt * 8 + (lane & 3) * 2;
                        *(uint32_t*)(stg + SWZ((uint32_t)(na * 128 + e * 2))) =
                            packbf2(d[j][nt][half * 2 + 0], d[j][nt][half * 2 + 1]);
                    }
                }
            }
            __syncthreads();
            uint4* dst = (uint4*)(g_Abf + (size_t)(b0 + j) * KTOT);
            #pragma unroll
            for (int i = tid; i < 1024; i += 256)
                dst[i] = *(uint4*)(stg + SWZ((uint32_t)(i * 16)));
        }
    }
}

// =====================================================================
// K5: bf16 mma GEMM, CTA tile 64x256 (N un-tiled), split-K x4,
//     warp tile 32x64, 2-stage pipeline, 2 CTAs/SM
// =====================================================================
__global__ __launch_bounds__(256, 2) void k_final_mma() {
    extern __shared__ __align__(128) char smf[];
    const uint32_t sb = smem_u32(smf);
    const int tid = threadIdx.x, lane = tid & 31, w = tid >> 5;
    const int bm = blockIdx.x * 64;
    const int kz = blockIdx.y;
    const int tbase = kz * 32;
    const int wm = (w & 1) * 32, wn = (w >> 1) * 64;
    float* part = g_part + (size_t)kz * BS * RNN;

    float d[2][8][4] = {};

    auto loadChunk = [&](int t, int s) {
        const __nv_bfloat16* Asrc = g_Abf + (size_t)bm * KTOT + (size_t)(tbase + t) * 64;
        #pragma unroll
        for (int i = 0; i < 2; i++) {
            int idx = tid + 256 * i;
            int row = idx >> 3, c = idx & 7;
            cp16(sb + s * 8192 + SWZ((uint32_t)(row * 128 + c * 16)),
                 Asrc + (size_t)row * KTOT + c * 8);
        }
        const __nv_bfloat16* Bsrc = g_Wfbf + (size_t)(tbase + t) * 64;
        #pragma unroll
        for (int i = 0; i < 8; i++) {
            int idx = tid + 256 * i;
            int row = idx >> 3, c = idx & 7;
            cp16(sb + 16384 + s * 32768 + SWZ((uint32_t)(row * 128 + c * 16)),
                 Bsrc + (size_t)row * KTOT + c * 8);
        }
        CP_COMMIT();
    };

    loadChunk(0, 0);
    for (int t = 0; t < 32; t++) {
        const int s = t & 1;
        if (t + 1 < 32) { loadChunk(t + 1, s ^ 1); CP_WAIT(1); }
        else            { CP_WAIT(0); }
        __syncthreads();

        const uint32_t abase = sb + s * 8192;
        const uint32_t bbase = sb + 16384 + s * 32768;
        #pragma unroll
        for (int ks = 0; ks < 4; ks++) {
            uint32_t a[2][4], b[8][2];
            #pragma unroll
            for (int mt = 0; mt < 2; mt++) {
                uint32_t byte = (uint32_t)((wm + mt * 16 + (lane & 15)) * 128
                                           + (lane >> 4) * 16 + ks * 32);
                LDSM_X4(a[mt][0], a[mt][1], a[mt][2], a[mt][3], abase + SWZ(byte));
            }
            #pragma unroll
            for (int nr = 0; nr < 4; nr++) {
                uint32_t byte = (uint32_t)((wn + nr * 16 + (lane & 15)) * 128
                                           + (lane >> 4) * 16 + ks * 32);
                uint32_t r0, r1, r2, r3;
                LDSM_X4(r0, r1, r2, r3, bbase + SWZ(byte));
                b[nr * 2 + 0][0] = r0; b[nr * 2 + 0][1] = r2;
                b[nr * 2 + 1][0] = r1; b[nr * 2 + 1][1] = r3;
            }
            #pragma unroll
            for (int mt = 0; mt < 2; mt++)
                #pragma unroll
                for (int nt = 0; nt < 8; nt++)
                    MMA16816(d[mt][nt], a[mt], b[nt]);
        }
        __syncthreads();
    }

    const int nbase = wn + (lane & 3) * 2;
    #pragma unroll
    for (int mt = 0; mt < 2; mt++) {
        #pragma unroll
        for (int half = 0; half < 2; half++) {
            int row = bm + wm + mt * 16 + half * 8 + (lane >> 2);
            #pragma unroll
            for (int nt = 0; nt < 8; nt++) {
                int col = nbase + nt * 8;
                *(float2*)&part[(size_t)row * RNN + col] =
                    make_float2(d[mt][nt][half * 2 + 0], d[mt][nt][half * 2 + 1]);
            }
        }
    }
}

// =====================================================================
// K6: out = sum(parts) + bt*S + bf
// =====================================================================
__global__ __launch_bounds__(256) void k_out(const float* __restrict__ bfv,
                                             float* __restrict__ out) {
    int i = blockIdx.x * 256 + threadIdx.x;
    int row = i >> 6;
    int col4 = (i & 63) * 4;
    const size_t stride4 = (size_t)BS * RNN / 4;
    float4 p0 = ((const float4*)g_part)[i];
    float4 p1 = ((const float4*)g_part)[i + stride4];
    float4 p2 = ((const float4*)g_part)[i + 2 * stride4];
    float4 p3 = ((const float4*)g_part)[i + 3 * stride4];
    float4 sv = *(const float4*)&g_S[col4];
    float4 bv = *(const float4*)&bfv[col4];
    float bt = g_bt[row];
    float4 o;
    o.x = (p0.x + p1.x) + (p2.x + p3.x) + bt * sv.x + bv.x;
    o.y = (p0.y + p1.y) + (p2.y + p3.y) + bt * sv.y + bv.y;
    o.z = (p0.z + p1.z) + (p2.z + p3.z) + bt * sv.z + bv.z;
    o.w = (p0.w + p1.w) + (p2.w + p3.w) + bt * sv.w + bv.w;
    ((float4*)out)[i] = o;
}

// =====================================================================
// launch
// =====================================================================
extern "C" void kernel_launch(void* const* d_in, const int* in_sizes, int n_in,
                              void* d_out, int out_size) {
    const float* obs  = (const float*)d_in[0];
    const float* Wq1  = (const float*)d_in[1];
    const float* bq1  = (const float*)d_in[2];
    const float* Wq2  = (const float*)d_in[3];
    const float* Wkm1 = (const float*)d_in[4];
    const float* bkm1 = (const float*)d_in[5];
    const float* Wkm2 = (const float*)d_in[6];
    const float* Wke  = (const float*)d_in[7];
    const float* Wka  = (const float*)d_in[8];
    const float* Wvm1 = (const float*)d_in[9];
    const float* bvm1 = (const float*)d_in[10];
    const float* Wvm2 = (const float*)d_in[11];
    const float* Wve  = (const float*)d_in[12];
    const float* Wva  = (const float*)d_in[13];
    const float* Wb1  = (const float*)d_in[14];
    const float* bb1  = (const float*)d_in[15];
    const float* Wb2  = (const float*)d_in[16];
    const float* bb2  = (const float*)d_in[17];
    const float* Wh1  = (const float*)d_in[18];
    const float* bh1  = (const float*)d_in[19];
    const float* Wh2  = (const float*)d_in[20];
    const float* bh2  = (const float*)d_in[21];
    const float* Wf   = (const float*)d_in[22];
    const float* bf   = (const float*)d_in[23];
    float* out = (float*)d_out;

    const int mega_smem = 75264;
    const int final_smem = 16384 + 2 * 32768;   // 81920
    cudaFuncSetAttribute(k_mega, cudaFuncAttributeMaxDynamicSharedMemorySize, mega_smem);
    cudaFuncSetAttribute(k_final_mma, cudaFuncAttributeMaxDynamicSharedMemorySize, final_smem);

    k_mega<<<833, 256, mega_smem>>>(obs, bb1, bh1, Wb1, Wh1, Wf, Wve, Wva,
                                    Wq1, bq1, Wq2, Wkm1, bkm1, Wkm2,
                                    Wvm1, bvm1, Wvm2, Wke, Wka);
    k_attn<<<2048, 256>>>(obs, Wb2, bb2, Wh2, bh2);
    k_final_mma<<<dim3(64, 4), 256, final_smem>>>();
    k_out<<<1024, 256>>>(bf, out);
}